// round 5
// baseline (speedup 1.0000x reference)
#include <cuda_runtime.h>
#include <cstdint>
#include <math.h>

// ---------------- problem constants ----------------
#define TLEN 1024
#define HID  2048
#define NKH  8
#define NVH  16
#define QKVZN 6144
#define SCALE_Q 0.08838834764831845f   // 128^-0.5

// ---------------- device scratch (no allocation allowed) ----------------
__device__ float g_qkvz[TLEN * QKVZN];
__device__ float g_ba  [TLEN * 32];
__device__ float g_q   [TLEN * 1024];
__device__ float g_k   [TLEN * 1024];
__device__ float g_v   [TLEN * 2048];
__device__ float g_qn  [NKH * TLEN * 128];
__device__ float g_kn  [NKH * TLEN * 128];
__device__ float g_scal[NVH * TLEN * 4];
__device__ float g_o   [TLEN * 2048];
__device__ float g_xn  [TLEN * 2048];
__device__ float g_dummy[128];

// ---------------- helpers ----------------
__device__ __forceinline__ float to_tf32(float x) {
    float r;
    asm("cvt.rna.tf32.f32 %0, %1;" : "=f"(r) : "f"(x));
    return r;
}

__device__ __forceinline__ void cp16(void* smem_dst, const void* gmem_src) {
    uint32_t s = (uint32_t)__cvta_generic_to_shared(smem_dst);
    asm volatile("cp.async.cg.shared.global [%0], [%1], 16;\n" :: "r"(s), "l"(gmem_src));
}
#define CP_COMMIT()  asm volatile("cp.async.commit_group;\n")
#define CP_WAIT(n)   asm volatile("cp.async.wait_group %0;\n" :: "n"(n))

// ---- packed f32x2 (sm_103a) ----
__device__ __forceinline__ uint64_t pk2(float lo, float hi) {
    uint64_t r; asm("mov.b64 %0, {%1, %2};" : "=l"(r) : "f"(lo), "f"(hi)); return r;
}
__device__ __forceinline__ void upk2(float& lo, float& hi, uint64_t v) {
    asm("mov.b64 {%0, %1}, %2;" : "=f"(lo), "=f"(hi) : "l"(v));
}
__device__ __forceinline__ uint64_t ffma2(uint64_t a, uint64_t b, uint64_t c) {
    uint64_t d; asm("fma.rn.f32x2 %0, %1, %2, %3;" : "=l"(d) : "l"(a), "l"(b), "l"(c)); return d;
}
__device__ __forceinline__ uint64_t fmul2(uint64_t a, uint64_t b) {
    uint64_t d; asm("mul.rn.f32x2 %0, %1, %2;" : "=l"(d) : "l"(a), "l"(b)); return d;
}
__device__ __forceinline__ uint64_t fadd2(uint64_t a, uint64_t b) {
    uint64_t d; asm("add.rn.f32x2 %0, %1, %2;" : "=l"(d) : "l"(a), "l"(b)); return d;
}

__device__ __forceinline__ void mma_tf32(float& d0, float& d1, float& d2, float& d3,
                                         uint32_t a0, uint32_t a1, uint32_t a2, uint32_t a3,
                                         uint32_t b0, uint32_t b1) {
    asm volatile(
        "mma.sync.aligned.m16n8k8.row.col.f32.tf32.tf32.f32 "
        "{%0,%1,%2,%3},{%4,%5,%6,%7},{%8,%9},{%0,%1,%2,%3};"
        : "+f"(d0), "+f"(d1), "+f"(d2), "+f"(d3)
        : "r"(a0), "r"(a1), "r"(a2), "r"(a3), "r"(b0), "r"(b1));
}

// ================= tf32 GEMM (cp.async 4-stage): C[M,N] = A[M,K]*B[N,K]^T =======
// BM=BN=128, BK=16, 256 threads (8 warps, each 64x32). Fragments rounded to tf32 in-reg.
#define GSTG 4
#define GSTF 5120
__global__ __launch_bounds__(256, 2)
void gemm_tf32_pipe(const float* __restrict__ A, const float* __restrict__ B,
                    float* __restrict__ C, int N, int K) {
    extern __shared__ float sm[];   // GSTG * GSTF floats = 80KB

    const int tid  = threadIdx.x;
    const int warp = tid >> 5, lane = tid & 31;
    const int wm = warp & 1, wn = warp >> 1;
    const int bm = blockIdx.y * 128, bn = blockIdx.x * 128;
    const int r0 = tid >> 2, c4 = tid & 3;

    const float* Ab = A + (size_t)bm * K;
    const float* Bb = B + (size_t)bn * K;
    const int nk = K >> 4;

    float acc[4][4][4];
#pragma unroll
    for (int i = 0; i < 4; i++)
#pragma unroll
        for (int j = 0; j < 4; j++)
#pragma unroll
            for (int l = 0; l < 4; l++) acc[i][j][l] = 0.f;

    auto preload = [&](int kt) {
        const int k0 = (kt << 4) + c4 * 4;
        float* st = sm + (kt & 3) * GSTF;
        cp16(st + r0 * 20 + c4 * 4,                Ab + (size_t)r0 * K + k0);
        cp16(st + (r0 + 64) * 20 + c4 * 4,         Ab + (size_t)(r0 + 64) * K + k0);
        cp16(st + 2560 + r0 * 20 + c4 * 4,         Bb + (size_t)r0 * K + k0);
        cp16(st + 2560 + (r0 + 64) * 20 + c4 * 4,  Bb + (size_t)(r0 + 64) * K + k0);
    };

    preload(0); CP_COMMIT();
    preload(1); CP_COMMIT();
    preload(2); CP_COMMIT();

    for (int kt = 0; kt < nk; kt++) {
        CP_WAIT(2);
        __syncthreads();
        const float* sAb = sm + (kt & 3) * GSTF;
        const float* sBb = sAb + 2560;
#pragma unroll
        for (int ks = 0; ks < 2; ks++) {
            uint32_t af[4][4];
#pragma unroll
            for (int mt = 0; mt < 4; mt++) {
                const float* p = sAb + (wm * 64 + mt * 16 + (lane >> 2)) * 20 + ks * 8 + (lane & 3);
                af[mt][0] = __float_as_uint(to_tf32(p[0]));
                af[mt][1] = __float_as_uint(to_tf32(p[8 * 20]));
                af[mt][2] = __float_as_uint(to_tf32(p[4]));
                af[mt][3] = __float_as_uint(to_tf32(p[8 * 20 + 4]));
            }
            uint32_t bf[4][2];
#pragma unroll
            for (int nt = 0; nt < 4; nt++) {
                const float* p = sBb + (wn * 32 + nt * 8 + (lane >> 2)) * 20 + ks * 8 + (lane & 3);
                bf[nt][0] = __float_as_uint(to_tf32(p[0]));
                bf[nt][1] = __float_as_uint(to_tf32(p[4]));
            }
#pragma unroll
            for (int mt = 0; mt < 4; mt++)
#pragma unroll
                for (int nt = 0; nt < 4; nt++)
                    mma_tf32(acc[mt][nt][0], acc[mt][nt][1], acc[mt][nt][2], acc[mt][nt][3],
                             af[mt][0], af[mt][1], af[mt][2], af[mt][3],
                             bf[nt][0], bf[nt][1]);
        }
        if (kt + 3 < nk) preload(kt + 3);
        CP_COMMIT();
    }

#pragma unroll
    for (int mt = 0; mt < 4; mt++) {
#pragma unroll
        for (int nt = 0; nt < 4; nt++) {
            int row = bm + wm * 64 + mt * 16 + (lane >> 2);
            int col = bn + wn * 32 + nt * 8 + (lane & 3) * 2;
            C[(size_t)row * N + col]           = acc[mt][nt][0];
            C[(size_t)row * N + col + 1]       = acc[mt][nt][1];
            C[(size_t)(row + 8) * N + col]     = acc[mt][nt][2];
            C[(size_t)(row + 8) * N + col + 1] = acc[mt][nt][3];
        }
    }
}

// ================= ba projection: [1024,32] = hs @ w_ba^T =================
__global__ __launch_bounds__(256)
void ba_kernel(const float* __restrict__ hs, const float* __restrict__ wba,
               float* __restrict__ out) {
    const int t = blockIdx.x;
    const int tid = threadIdx.x;
    const int n = tid >> 3, s = tid & 7;
    const float4* h4 = (const float4*)(hs + (size_t)t * HID + s * 256);
    const float4* w4 = (const float4*)(wba + (size_t)n * HID + s * 256);
    float acc = 0.f;
#pragma unroll 8
    for (int i = 0; i < 64; i++) {
        float4 a = h4[i], b = w4[i];
        acc += a.x * b.x + a.y * b.y + a.z * b.z + a.w * b.w;
    }
    acc += __shfl_xor_sync(0xffffffffu, acc, 1);
    acc += __shfl_xor_sync(0xffffffffu, acc, 2);
    acc += __shfl_xor_sync(0xffffffffu, acc, 4);
    if (s == 0) out[t * 32 + n] = acc;
}

// ================= depthwise causal conv1d + silu =================
__global__ __launch_bounds__(256)
void conv_kernel(const float* __restrict__ qkvz, const float* __restrict__ convw,
                 float* __restrict__ gq, float* __restrict__ gk, float* __restrict__ gv) {
    const int cb = blockIdx.x;
    const int t0 = blockIdx.y * 32;
    __shared__ float sx[35][128];

    int colbase;
    const int chbase = cb * 128;
    if (cb < 8)        colbase = cb * 768;
    else if (cb < 16)  colbase = (cb - 8) * 768 + 128;
    else { int vh = cb - 16; colbase = (vh >> 1) * 768 + 256 + (vh & 1) * 128; }

    for (int idx = threadIdx.x; idx < 35 * 128; idx += 256) {
        const int r = idx >> 7, c = idx & 127;
        const int t = t0 + r - 3;
        sx[r][c] = (t >= 0) ? qkvz[(size_t)t * QKVZN + colbase + c] : 0.f;
    }
    __syncthreads();

    for (int idx = threadIdx.x; idx < 32 * 128; idx += 256) {
        const int r = idx >> 7, c = idx & 127;
        const int ch = chbase + c;
        const float4 w = *(const float4*)(convw + ch * 4);
        float y = sx[r][c] * w.x + sx[r + 1][c] * w.y + sx[r + 2][c] * w.z + sx[r + 3][c] * w.w;
        y = y / (1.f + expf(-y));
        const int t = t0 + r;
        if (ch < 1024)      gq[t * 1024 + ch] = y;
        else if (ch < 2048) gk[t * 1024 + ch - 1024] = y;
        else                gv[t * 2048 + ch - 2048] = y;
    }
}

// ================= prep: l2-norm q,k, qk dot, gates =================
__global__ __launch_bounds__(128)
void prep_kernel(const float* __restrict__ gq, const float* __restrict__ gk,
                 const float* __restrict__ gba, const float* __restrict__ A_log,
                 const float* __restrict__ dt_bias,
                 float* __restrict__ gqn, float* __restrict__ gkn,
                 float* __restrict__ gscal) {
    const int t = blockIdx.x, kh = blockIdx.y, i = threadIdx.x;
    __shared__ float red[4];

    const float q = gq[t * 1024 + kh * 128 + i];
    const float k = gk[t * 1024 + kh * 128 + i];

    float v, s_qq, s_kk, s_qk;

    v = q * q;
#pragma unroll
    for (int m = 16; m; m >>= 1) v += __shfl_xor_sync(0xffffffffu, v, m);
    if ((i & 31) == 0) red[i >> 5] = v;
    __syncthreads();
    s_qq = red[0] + red[1] + red[2] + red[3];
    __syncthreads();

    v = k * k;
#pragma unroll
    for (int m = 16; m; m >>= 1) v += __shfl_xor_sync(0xffffffffu, v, m);
    if ((i & 31) == 0) red[i >> 5] = v;
    __syncthreads();
    s_kk = red[0] + red[1] + red[2] + red[3];
    __syncthreads();

    const float qn = q * rsqrtf(s_qq + 1e-6f) * SCALE_Q;
    const float kn = k * rsqrtf(s_kk + 1e-6f);
    gqn[((size_t)kh * TLEN + t) * 128 + i] = qn;
    gkn[((size_t)kh * TLEN + t) * 128 + i] = kn;

    v = qn * kn;
#pragma unroll
    for (int m = 16; m; m >>= 1) v += __shfl_xor_sync(0xffffffffu, v, m);
    if ((i & 31) == 0) red[i >> 5] = v;
    __syncthreads();
    s_qk = red[0] + red[1] + red[2] + red[3];

    if (i < 2) {
        const int vh = kh * 2 + i;
        const float b = gba[t * 32 + kh * 4 + i];
        const float a = gba[t * 32 + kh * 4 + 2 + i];
        const float beta = 1.f / (1.f + expf(-b));
        const float x = a + dt_bias[vh];
        const float sp = (x > 20.f) ? x : log1pf(expf(x));
        const float g = -expf(A_log[vh]) * sp;
        float4 sc;
        sc.x = expf(g); sc.y = beta; sc.z = s_qk; sc.w = 0.f;
        *(float4*)(gscal + ((size_t)vh * TLEN + t) * 4) = sc;
    }
}

// ================= dummy (profiler alignment) =================
__global__ void dummy_kernel(const float* __restrict__ in, float* __restrict__ out) {
    out[threadIdx.x] = in[threadIdx.x];
}

// ================= gated delta-rule scan (f32x2) =================
// grid (8 vblocks, 16 heads), 128 threads = 8 kgroups x 16 vcols.
// 16-slot ring, prefetch distance 12 steps, sync every 4 steps.
__global__ __launch_bounds__(128, 1)
void scan_kernel(const float* __restrict__ gqn, const float* __restrict__ gkn,
                 const float* __restrict__ gv, const float* __restrict__ gscal,
                 float* __restrict__ go) {
    const int vb = blockIdx.x;
    const int vh = blockIdx.y;
    const int kh = vh >> 1;
    const int tid = threadIdx.x;
    const int kg = tid & 7;
    const int vc = tid >> 3;

    __shared__ __align__(16) float ring[16][276];  // k[128], q[128], v[16], scal[4]

    const float* kbase = gkn + (size_t)kh * TLEN * 128;
    const float* qbase = gqn + (size_t)kh * TLEN * 128;
    const float* vbase = gv + vh * 128 + vb * 16;
    const float* sbase = gscal + (size_t)vh * TLEN * 4;

    uint64_t Sp[8];
#pragma unroll
    for (int i = 0; i < 8; i++) Sp[i] = 0ull;

    auto prefetch = [&](int tt) {
        if (tt < TLEN) {
            float* sl = ring[tt & 15];
            if (tid < 32)       cp16(sl + tid * 4, kbase + (size_t)tt * 128 + tid * 4);
            else if (tid < 64)  cp16(sl + 128 + (tid - 32) * 4, qbase + (size_t)tt * 128 + (tid - 32) * 4);
            else if (tid < 68)  cp16(sl + 256 + (tid - 64) * 4, vbase + (size_t)tt * 2048 + (tid - 64) * 4);
            else if (tid == 68) cp16(sl + 272, sbase + (size_t)tt * 4);
        }
        CP_COMMIT();
    };

    for (int p = 0; p < 12; p++) prefetch(p);

    const int obase = vh * 128 + vb * 16 + vc;

    for (int t = 0; t < TLEN; t += 4) {
        CP_WAIT(8);
        __syncthreads();
#pragma unroll
        for (int u = 0; u < 4; u++) {
            const int tt = t + u;
            const float* sl = ring[tt & 15];

            // load k,q slices as packed pairs
            uint64_t kk[8], qq[8];
            const double2* kp = (const double2*)(sl + kg * 16);
            const double2* qp = (const double2*)(sl + 128 + kg * 16);
#pragma unroll
            for (int j = 0; j < 4; j++) {
                double2 dk = kp[j], dq = qp[j];
                kk[2 * j]     = __double_as_longlong(dk.x);
                kk[2 * j + 1] = __double_as_longlong(dk.y);
                qq[2 * j]     = __double_as_longlong(dq.x);
                qq[2 * j + 1] = __double_as_longlong(dq.y);
            }

            const float4 sc = *(const float4*)(sl + 272);   // eg, beta, qk
            const float eg = sc.x, beta = sc.y, qk = sc.z;
            const float vt = sl[256 + vc];
            const float vtb = vt * beta;
            const float negb = -eg * beta;
            const uint64_t eg2 = pk2(eg, eg);

            // off-path: decayed state
            uint64_t eS[8];
#pragma unroll
            for (int j = 0; j < 8; j++) eS[j] = fmul2(eg2, Sp[j]);

            // dots (r1 critical, r2 off-path)
            uint64_t c0 = 0ull, c1 = 0ull, d0 = 0ull, d1 = 0ull;
#pragma unroll
            for (int j = 0; j < 4; j++) {
                c0 = ffma2(kk[j], Sp[j], c0);
                c1 = ffma2(kk[j + 4], Sp[j + 4], c1);
                d0 = ffma2(qq[j], Sp[j], d0);
                d1 = ffma2(qq[j + 4], Sp[j + 4], d1);
            }
            float lo, hi;
            upk2(lo, hi, fadd2(c0, c1));
            float r1 = lo + hi;
            float l2, h2;
            upk2(l2, h2, fadd2(d0, d1));
            float r2 = l2 + h2;

            r1 += __shfl_xor_sync(0xffffffffu, r1, 1);
            r2 += __shfl_xor_sync(0xffffffffu, r2, 1);
            r1 += __shfl_xor_sync(0xffffffffu, r1, 2);
            r2 += __shfl_xor_sync(0xffffffffu, r2, 2);
            r1 += __shfl_xor_sync(0xffffffffu, r1, 4);
            r2 += __shfl_xor_sync(0xffffffffu, r2, 4);

            const float delta = fmaf(negb, r1, vtb);
            const uint64_t dl2 = pk2(delta, delta);
#pragma unroll
            for (int j = 0; j < 8; j++) Sp[j] = ffma2(kk[j], dl2, eS[j]);

            if (kg == 0) go[(size_t)tt * 2048 + obase] = fmaf(eg, r2, qk * delta);
        }
        prefetch(t + 12);
        prefetch(t + 13);
        prefetch(t + 14);
        prefetch(t + 15);
    }
}

// ================= gated RMSNorm =================
__global__ __launch_bounds__(128)
void rmsnorm_kernel(const float* __restrict__ go, const float* __restrict__ qkvz,
                    const float* __restrict__ nw, float* __restrict__ gxn) {
    const int t = blockIdx.x, vh = blockIdx.y, i = threadIdx.x;
    __shared__ float red[4];
    const float o = go[(size_t)t * 2048 + vh * 128 + i];
    const float z = qkvz[(size_t)t * QKVZN + (vh >> 1) * 768 + 512 + (vh & 1) * 128 + i];
    const float xf = o * (z / (1.f + expf(-z)));
    float v = xf * xf;
#pragma unroll
    for (int m = 16; m; m >>= 1) v += __shfl_xor_sync(0xffffffffu, v, m);
    if ((i & 31) == 0) red[i >> 5] = v;
    __syncthreads();
    const float s = red[0] + red[1] + red[2] + red[3];
    gxn[(size_t)t * 2048 + vh * 128 + i] = xf * rsqrtf(s * (1.f / 128.f) + 1e-6f) * nw[i];
}

// ================= launch =================
extern "C" void kernel_launch(void* const* d_in, const int* in_sizes, int n_in,
                              void* d_out, int out_size) {
    const float* hs      = (const float*)d_in[0];
    const float* w_qkvz  = (const float*)d_in[1];
    const float* w_ba    = (const float*)d_in[2];
    const float* conv_w  = (const float*)d_in[3];
    const float* dt_bias = (const float*)d_in[4];
    const float* A_log   = (const float*)d_in[5];
    const float* norm_w  = (const float*)d_in[6];
    const float* w_out   = (const float*)d_in[7];
    float* out = (float*)d_out;

    float *p_qkvz, *p_ba, *p_q, *p_k, *p_v, *p_qn, *p_kn, *p_scal, *p_o, *p_xn, *p_dum;
    cudaGetSymbolAddress((void**)&p_qkvz, g_qkvz);
    cudaGetSymbolAddress((void**)&p_ba,   g_ba);
    cudaGetSymbolAddress((void**)&p_q,    g_q);
    cudaGetSymbolAddress((void**)&p_k,    g_k);
    cudaGetSymbolAddress((void**)&p_v,    g_v);
    cudaGetSymbolAddress((void**)&p_qn,   g_qn);
    cudaGetSymbolAddress((void**)&p_kn,   g_kn);
    cudaGetSymbolAddress((void**)&p_scal, g_scal);
    cudaGetSymbolAddress((void**)&p_o,    g_o);
    cudaGetSymbolAddress((void**)&p_xn,   g_xn);
    cudaGetSymbolAddress((void**)&p_dum,  g_dummy);

    static int smem_set = 0;
    if (!smem_set) {
        cudaFuncSetAttribute(gemm_tf32_pipe, cudaFuncAttributeMaxDynamicSharedMemorySize,
                             GSTG * GSTF * 4);
        smem_set = 1;
    }

    // launch 0: qkvz projection [1024,6144]
    gemm_tf32_pipe<<<dim3(QKVZN / 128, TLEN / 128), 256, GSTG * GSTF * 4>>>(
        hs, w_qkvz, p_qkvz, QKVZN, HID);
    // launch 1: ba projection
    ba_kernel<<<TLEN, 256>>>(hs, w_ba, p_ba);
    // launch 2: conv + silu
    conv_kernel<<<dim3(32, 32), 256>>>(p_qkvz, conv_w, p_q, p_k, p_v);
    // launch 3: norm + gates
    prep_kernel<<<dim3(TLEN, NKH), 128>>>(p_q, p_k, p_ba, A_log, dt_bias, p_qn, p_kn, p_scal);
    // launch 4: dummy (aligns ncu -s 5 onto the scan)
    dummy_kernel<<<1, 128>>>(norm_w, p_dum);
    // launch 5: delta-rule scan
    scan_kernel<<<dim3(8, NVH), 128>>>(p_qn, p_kn, p_v, p_scal, p_o);
    // launch 6: gated rmsnorm
    rmsnorm_kernel<<<dim3(TLEN, NVH), 128>>>(p_o, p_qkvz, norm_w, p_xn);
    // launch 7: output projection [1024,2048]
    gemm_tf32_pipe<<<dim3(HID / 128, TLEN / 128), 256, GSTG * GSTF * 4>>>(
        p_xn, w_out, out, HID, HID);
}

// round 7
// speedup vs baseline: 1.6798x; 1.6798x over previous
#include <cuda_runtime.h>
#include <cstdint>
#include <math.h>

// ---------------- problem constants ----------------
#define TLEN 1024
#define HID  2048
#define NKH  8
#define NVH  16
#define QKVZN 6144
#define SCALE_Q 0.08838834764831845f   // 128^-0.5

// ---------------- device scratch (no allocation allowed) ----------------
__device__ float g_qkvz[TLEN * QKVZN];
__device__ float g_ba  [TLEN * 32];
__device__ float g_v   [TLEN * 2048];
__device__ float g_qn  [NKH * TLEN * 128];
__device__ float g_kn  [NKH * TLEN * 128];
__device__ float g_scal[NVH * TLEN * 4];
__device__ float g_o   [TLEN * 2048];
__device__ float g_xn  [TLEN * 2048];
__device__ float g_hsr [TLEN * HID];        // tf32-rounded hidden states
__device__ float g_wqr [QKVZN * HID];       // tf32-rounded w_qkvz
__device__ float g_wor [HID * HID];         // tf32-rounded w_out

// ---------------- helpers ----------------
__device__ __forceinline__ float to_tf32(float x) {
    float r;
    asm("cvt.rna.tf32.f32 %0, %1;" : "=f"(r) : "f"(x));
    return r;
}

__device__ __forceinline__ void cp16(void* smem_dst, const void* gmem_src) {
    uint32_t s = (uint32_t)__cvta_generic_to_shared(smem_dst);
    asm volatile("cp.async.cg.shared.global [%0], [%1], 16;\n" :: "r"(s), "l"(gmem_src));
}
#define CP_COMMIT()  asm volatile("cp.async.commit_group;\n")
#define CP_WAIT(n)   asm volatile("cp.async.wait_group %0;\n" :: "n"(n))

__device__ __forceinline__ void mma_tf32(float& d0, float& d1, float& d2, float& d3,
                                         uint32_t a0, uint32_t a1, uint32_t a2, uint32_t a3,
                                         uint32_t b0, uint32_t b1) {
    asm volatile(
        "mma.sync.aligned.m16n8k8.row.col.f32.tf32.tf32.f32 "
        "{%0,%1,%2,%3},{%4,%5,%6,%7},{%8,%9},{%0,%1,%2,%3};"
        : "+f"(d0), "+f"(d1), "+f"(d2), "+f"(d3)
        : "r"(a0), "r"(a1), "r"(a2), "r"(a3), "r"(b0), "r"(b1));
}

// ================= fused pre-pass: ba projection + tf32 rounding =================
// blocks 0..1023: ba for t=blockIdx.x. blocks 1024+: grid-stride rna-round of
// hs -> g_hsr, w_qkvz -> g_wqr, w_out -> g_wor.
#define NH4 (TLEN * HID / 4)
#define NQ4 (QKVZN * HID / 4)
#define NO4 (HID * HID / 4)
#define PREB 4608
__global__ __launch_bounds__(256)
void pre_kernel(const float* __restrict__ hs, const float* __restrict__ wba,
                float* __restrict__ ba_out,
                float4* __restrict__ hsr, float4* __restrict__ wqr,
                float4* __restrict__ wor, const float4* __restrict__ wq4,
                const float4* __restrict__ wo4) {
    const int tid = threadIdx.x;
    if (blockIdx.x < 1024) {
        const int t = blockIdx.x;
        const int n = tid >> 3, s = tid & 7;
        const float4* h4 = (const float4*)(hs + (size_t)t * HID + s * 256);
        const float4* w4 = (const float4*)(wba + (size_t)n * HID + s * 256);
        float acc = 0.f;
#pragma unroll 8
        for (int i = 0; i < 64; i++) {
            float4 a = h4[i], b = w4[i];
            acc += a.x * b.x + a.y * b.y + a.z * b.z + a.w * b.w;
        }
        acc += __shfl_xor_sync(0xffffffffu, acc, 1);
        acc += __shfl_xor_sync(0xffffffffu, acc, 2);
        acc += __shfl_xor_sync(0xffffffffu, acc, 4);
        if (s == 0) ba_out[t * 32 + n] = acc;
    } else {
        const float4* hs4 = (const float4*)hs;
        const int stride = (PREB - 1024) * 256;
        for (int i = (blockIdx.x - 1024) * 256 + tid; i < NH4 + NQ4 + NO4; i += stride) {
            float4 v;
            if (i < NH4) {
                v = hs4[i];
                v.x = to_tf32(v.x); v.y = to_tf32(v.y); v.z = to_tf32(v.z); v.w = to_tf32(v.w);
                hsr[i] = v;
            } else if (i < NH4 + NQ4) {
                v = wq4[i - NH4];
                v.x = to_tf32(v.x); v.y = to_tf32(v.y); v.z = to_tf32(v.z); v.w = to_tf32(v.w);
                wqr[i - NH4] = v;
            } else {
                v = wo4[i - NH4 - NQ4];
                v.x = to_tf32(v.x); v.y = to_tf32(v.y); v.z = to_tf32(v.z); v.w = to_tf32(v.w);
                wor[i - NH4 - NQ4] = v;
            }
        }
    }
}

// ================= tf32 GEMM (cp.async 4-stage): C[M,N] = A[M,K]*B[N,K]^T =======
// BM=BN=128, BK=16, 256 threads (8 warps, each 64x32). Inputs pre-rounded rna.
#define GSTG 4
#define GSTF 5120
__global__ __launch_bounds__(256, 2)
void gemm_tf32_pipe(const float* __restrict__ A, const float* __restrict__ B,
                    float* __restrict__ C, int N, int K) {
    extern __shared__ float sm[];   // GSTG * GSTF floats = 80KB

    const int tid  = threadIdx.x;
    const int warp = tid >> 5, lane = tid & 31;
    const int wm = warp & 1, wn = warp >> 1;
    const int bm = blockIdx.y * 128, bn = blockIdx.x * 128;
    const int r0 = tid >> 2, c4 = tid & 3;

    const float* Ab = A + (size_t)bm * K;
    const float* Bb = B + (size_t)bn * K;
    const int nk = K >> 4;

    float acc[4][4][4];
#pragma unroll
    for (int i = 0; i < 4; i++)
#pragma unroll
        for (int j = 0; j < 4; j++)
#pragma unroll
            for (int l = 0; l < 4; l++) acc[i][j][l] = 0.f;

    auto preload = [&](int kt) {
        const int k0 = (kt << 4) + c4 * 4;
        float* st = sm + (kt & 3) * GSTF;
        cp16(st + r0 * 20 + c4 * 4,                Ab + (size_t)r0 * K + k0);
        cp16(st + (r0 + 64) * 20 + c4 * 4,         Ab + (size_t)(r0 + 64) * K + k0);
        cp16(st + 2560 + r0 * 20 + c4 * 4,         Bb + (size_t)r0 * K + k0);
        cp16(st + 2560 + (r0 + 64) * 20 + c4 * 4,  Bb + (size_t)(r0 + 64) * K + k0);
    };

    preload(0); CP_COMMIT();
    preload(1); CP_COMMIT();
    preload(2); CP_COMMIT();

    for (int kt = 0; kt < nk; kt++) {
        CP_WAIT(2);
        __syncthreads();
        const float* sAb = sm + (kt & 3) * GSTF;
        const float* sBb = sAb + 2560;
#pragma unroll
        for (int ks = 0; ks < 2; ks++) {
            uint32_t af[4][4];
#pragma unroll
            for (int mt = 0; mt < 4; mt++) {
                const float* p = sAb + (wm * 64 + mt * 16 + (lane >> 2)) * 20 + ks * 8 + (lane & 3);
                af[mt][0] = __float_as_uint(p[0]);
                af[mt][1] = __float_as_uint(p[8 * 20]);
                af[mt][2] = __float_as_uint(p[4]);
                af[mt][3] = __float_as_uint(p[8 * 20 + 4]);
            }
            uint32_t bf[4][2];
#pragma unroll
            for (int nt = 0; nt < 4; nt++) {
                const float* p = sBb + (wn * 32 + nt * 8 + (lane >> 2)) * 20 + ks * 8 + (lane & 3);
                bf[nt][0] = __float_as_uint(p[0]);
                bf[nt][1] = __float_as_uint(p[4]);
            }
#pragma unroll
            for (int mt = 0; mt < 4; mt++)
#pragma unroll
                for (int nt = 0; nt < 4; nt++)
                    mma_tf32(acc[mt][nt][0], acc[mt][nt][1], acc[mt][nt][2], acc[mt][nt][3],
                             af[mt][0], af[mt][1], af[mt][2], af[mt][3],
                             bf[nt][0], bf[nt][1]);
        }
        if (kt + 3 < nk) preload(kt + 3);
        CP_COMMIT();
    }

#pragma unroll
    for (int mt = 0; mt < 4; mt++) {
#pragma unroll
        for (int nt = 0; nt < 4; nt++) {
            int row = bm + wm * 64 + mt * 16 + (lane >> 2);
            int col = bn + wn * 32 + nt * 8 + (lane & 3) * 2;
            C[(size_t)row * N + col]           = acc[mt][nt][0];
            C[(size_t)row * N + col + 1]       = acc[mt][nt][1];
            C[(size_t)(row + 8) * N + col]     = acc[mt][nt][2];
            C[(size_t)(row + 8) * N + col + 1] = acc[mt][nt][3];
        }
    }
}

// ================= fused conv1d+silu + l2-norm + gates =================
// grid (1024, 8), 128 threads. Block (t, kh): conv q/k + both v heads,
// l2 norms, qk dot, gate scales.
__global__ __launch_bounds__(128)
void convprep_kernel(const float* __restrict__ qkvz, const float* __restrict__ convw,
                     const float* __restrict__ gba, const float* __restrict__ A_log,
                     const float* __restrict__ dt_bias,
                     float* __restrict__ gqn, float* __restrict__ gkn,
                     float* __restrict__ gv, float* __restrict__ gscal) {
    const int t = blockIdx.x, kh = blockIdx.y, i = threadIdx.x;
    __shared__ float red[4];
    const int base = kh * 768;

    float xq[4], xk[4], xv0[4], xv1[4];
#pragma unroll
    for (int tau = 0; tau < 4; tau++) {
        const int tt = t - 3 + tau;
        const bool ok = (tt >= 0);
        const float* r = qkvz + (size_t)(ok ? tt : 0) * QKVZN + base;
        xq[tau]  = ok ? r[i]       : 0.f;
        xk[tau]  = ok ? r[128 + i] : 0.f;
        xv0[tau] = ok ? r[256 + i] : 0.f;
        xv1[tau] = ok ? r[384 + i] : 0.f;
    }
    const float4 wq  = *(const float4*)(convw + (size_t)(kh * 128 + i) * 4);
    const float4 wk  = *(const float4*)(convw + (size_t)(1024 + kh * 128 + i) * 4);
    const float4 wv0 = *(const float4*)(convw + (size_t)(2048 + (2 * kh) * 128 + i) * 4);
    const float4 wv1 = *(const float4*)(convw + (size_t)(2048 + (2 * kh + 1) * 128 + i) * 4);

    float q  = xq[0] * wq.x + xq[1] * wq.y + xq[2] * wq.z + xq[3] * wq.w;
    float k  = xk[0] * wk.x + xk[1] * wk.y + xk[2] * wk.z + xk[3] * wk.w;
    float v0 = xv0[0] * wv0.x + xv0[1] * wv0.y + xv0[2] * wv0.z + xv0[3] * wv0.w;
    float v1 = xv1[0] * wv1.x + xv1[1] * wv1.y + xv1[2] * wv1.z + xv1[3] * wv1.w;
    q  = q  / (1.f + expf(-q));
    k  = k  / (1.f + expf(-k));
    v0 = v0 / (1.f + expf(-v0));
    v1 = v1 / (1.f + expf(-v1));

    gv[(size_t)t * 2048 + (2 * kh) * 128 + i]     = v0;
    gv[(size_t)t * 2048 + (2 * kh + 1) * 128 + i] = v1;

    float v, s_qq, s_kk, s_qk;

    v = q * q;
#pragma unroll
    for (int m = 16; m; m >>= 1) v += __shfl_xor_sync(0xffffffffu, v, m);
    if ((i & 31) == 0) red[i >> 5] = v;
    __syncthreads();
    s_qq = red[0] + red[1] + red[2] + red[3];
    __syncthreads();

    v = k * k;
#pragma unroll
    for (int m = 16; m; m >>= 1) v += __shfl_xor_sync(0xffffffffu, v, m);
    if ((i & 31) == 0) red[i >> 5] = v;
    __syncthreads();
    s_kk = red[0] + red[1] + red[2] + red[3];
    __syncthreads();

    const float qn = q * rsqrtf(s_qq + 1e-6f) * SCALE_Q;
    const float kn = k * rsqrtf(s_kk + 1e-6f);
    gqn[((size_t)kh * TLEN + t) * 128 + i] = qn;
    gkn[((size_t)kh * TLEN + t) * 128 + i] = kn;

    v = qn * kn;
#pragma unroll
    for (int m = 16; m; m >>= 1) v += __shfl_xor_sync(0xffffffffu, v, m);
    if ((i & 31) == 0) red[i >> 5] = v;
    __syncthreads();
    s_qk = red[0] + red[1] + red[2] + red[3];

    if (i < 2) {
        const int vh = kh * 2 + i;
        const float b = gba[t * 32 + kh * 4 + i];
        const float a = gba[t * 32 + kh * 4 + 2 + i];
        const float beta = 1.f / (1.f + expf(-b));
        const float x = a + dt_bias[vh];
        const float sp = (x > 20.f) ? x : log1pf(expf(x));
        const float g = -expf(A_log[vh]) * sp;
        float4 sc;
        sc.x = expf(g); sc.y = beta; sc.z = s_qk; sc.w = 0.f;
        *(float4*)(gscal + ((size_t)vh * TLEN + t) * 4) = sc;
    }
}

// ================= gated delta-rule scan =================
// grid (8 vblocks, 16 heads), 128 threads = 8 kgroups x 16 vcols
__global__ __launch_bounds__(128, 1)
void scan_kernel(const float* __restrict__ gqn, const float* __restrict__ gkn,
                 const float* __restrict__ gv, const float* __restrict__ gscal,
                 float* __restrict__ go) {
    const int vb = blockIdx.x;
    const int vh = blockIdx.y;
    const int kh = vh >> 1;
    const int tid = threadIdx.x;
    const int kg = tid & 7;
    const int vc = tid >> 3;

    __shared__ float ring[8][276];

    const float* kbase = gkn + (size_t)kh * TLEN * 128;
    const float* qbase = gqn + (size_t)kh * TLEN * 128;
    const float* vbase = gv + vh * 128 + vb * 16;
    const float* sbase = gscal + (size_t)vh * TLEN * 4;

    float S[16];
#pragma unroll
    for (int i = 0; i < 16; i++) S[i] = 0.f;

    auto prefetch = [&](int tt) {
        if (tt < TLEN) {
            float* sl = ring[tt & 7];
            if (tid < 32)       cp16(sl + tid * 4, kbase + (size_t)tt * 128 + tid * 4);
            else if (tid < 64)  cp16(sl + 128 + (tid - 32) * 4, qbase + (size_t)tt * 128 + (tid - 32) * 4);
            else if (tid < 68)  cp16(sl + 256 + (tid - 64) * 4, vbase + (size_t)tt * 2048 + (tid - 64) * 4);
            else if (tid == 68) cp16(sl + 272, sbase + (size_t)tt * 4);
        }
        CP_COMMIT();
    };

    for (int p = 0; p < 6; p++) prefetch(p);

    const int obase = vh * 128 + vb * 16 + vc;

    for (int t = 0; t < TLEN; t += 2) {
        CP_WAIT(4);
        __syncthreads();
#pragma unroll
        for (int u = 0; u < 2; u++) {
            const int tt = t + u;
            const float* sl = ring[tt & 7];
            float4 kk[4], qq[4];
            const float4* kp = (const float4*)(sl + kg * 16);
            const float4* qp = (const float4*)(sl + 128 + kg * 16);
#pragma unroll
            for (int j = 0; j < 4; j++) { kk[j] = kp[j]; qq[j] = qp[j]; }

            float r1a = 0.f, r1b = 0.f, r2a = 0.f, r2b = 0.f;
#pragma unroll
            for (int j = 0; j < 2; j++) {
                r1a += kk[j].x * S[j * 4 + 0]; r2a += qq[j].x * S[j * 4 + 0];
                r1a += kk[j].y * S[j * 4 + 1]; r2a += qq[j].y * S[j * 4 + 1];
                r1a += kk[j].z * S[j * 4 + 2]; r2a += qq[j].z * S[j * 4 + 2];
                r1a += kk[j].w * S[j * 4 + 3]; r2a += qq[j].w * S[j * 4 + 3];
            }
#pragma unroll
            for (int j = 2; j < 4; j++) {
                r1b += kk[j].x * S[j * 4 + 0]; r2b += qq[j].x * S[j * 4 + 0];
                r1b += kk[j].y * S[j * 4 + 1]; r2b += qq[j].y * S[j * 4 + 1];
                r1b += kk[j].z * S[j * 4 + 2]; r2b += qq[j].z * S[j * 4 + 2];
                r1b += kk[j].w * S[j * 4 + 3]; r2b += qq[j].w * S[j * 4 + 3];
            }
            float r1 = r1a + r1b, r2 = r2a + r2b;
            r1 += __shfl_xor_sync(0xffffffffu, r1, 1);
            r2 += __shfl_xor_sync(0xffffffffu, r2, 1);
            r1 += __shfl_xor_sync(0xffffffffu, r1, 2);
            r2 += __shfl_xor_sync(0xffffffffu, r2, 2);
            r1 += __shfl_xor_sync(0xffffffffu, r1, 4);
            r2 += __shfl_xor_sync(0xffffffffu, r2, 4);

            const float4 sc = *(const float4*)(sl + 272);
            const float eg = sc.x, beta = sc.y, qk = sc.z;
            const float vt = sl[256 + vc];
            const float vtb = vt * beta;
            const float negb = -eg * beta;

            float eS[16];
#pragma unroll
            for (int j = 0; j < 16; j++) eS[j] = eg * S[j];

            const float delta = fmaf(negb, r1, vtb);
            if (kg == 0) go[(size_t)tt * 2048 + obase] = fmaf(eg, r2, qk * delta);
#pragma unroll
            for (int j = 0; j < 4; j++) {
                S[j * 4 + 0] = fmaf(kk[j].x, delta, eS[j * 4 + 0]);
                S[j * 4 + 1] = fmaf(kk[j].y, delta, eS[j * 4 + 1]);
                S[j * 4 + 2] = fmaf(kk[j].z, delta, eS[j * 4 + 2]);
                S[j * 4 + 3] = fmaf(kk[j].w, delta, eS[j * 4 + 3]);
            }
        }
        prefetch(t + 6);
        prefetch(t + 7);
    }
}

// ================= gated RMSNorm (emits tf32-rounded xn) =================
__global__ __launch_bounds__(128)
void rmsnorm_kernel(const float* __restrict__ go, const float* __restrict__ qkvz,
                    const float* __restrict__ nw, float* __restrict__ gxn) {
    const int t = blockIdx.x, vh = blockIdx.y, i = threadIdx.x;
    __shared__ float red[4];
    const float o = go[(size_t)t * 2048 + vh * 128 + i];
    const float z = qkvz[(size_t)t * QKVZN + (vh >> 1) * 768 + 512 + (vh & 1) * 128 + i];
    const float xf = o * (z / (1.f + expf(-z)));
    float v = xf * xf;
#pragma unroll
    for (int m = 16; m; m >>= 1) v += __shfl_xor_sync(0xffffffffu, v, m);
    if ((i & 31) == 0) red[i >> 5] = v;
    __syncthreads();
    const float s = red[0] + red[1] + red[2] + red[3];
    gxn[(size_t)t * 2048 + vh * 128 + i] =
        to_tf32(xf * rsqrtf(s * (1.f / 128.f) + 1e-6f) * nw[i]);
}

// ================= launch =================
extern "C" void kernel_launch(void* const* d_in, const int* in_sizes, int n_in,
                              void* d_out, int out_size) {
    const float* hs      = (const float*)d_in[0];
    const float* w_qkvz  = (const float*)d_in[1];
    const float* w_ba    = (const float*)d_in[2];
    const float* conv_w  = (const float*)d_in[3];
    const float* dt_bias = (const float*)d_in[4];
    const float* A_log   = (const float*)d_in[5];
    const float* norm_w  = (const float*)d_in[6];
    const float* w_out   = (const float*)d_in[7];
    float* out = (float*)d_out;

    float *p_qkvz, *p_ba, *p_v, *p_qn, *p_kn, *p_scal, *p_o, *p_xn;
    float *p_hsr, *p_wqr, *p_wor;
    cudaGetSymbolAddress((void**)&p_qkvz, g_qkvz);
    cudaGetSymbolAddress((void**)&p_ba,   g_ba);
    cudaGetSymbolAddress((void**)&p_v,    g_v);
    cudaGetSymbolAddress((void**)&p_qn,   g_qn);
    cudaGetSymbolAddress((void**)&p_kn,   g_kn);
    cudaGetSymbolAddress((void**)&p_scal, g_scal);
    cudaGetSymbolAddress((void**)&p_o,    g_o);
    cudaGetSymbolAddress((void**)&p_xn,   g_xn);
    cudaGetSymbolAddress((void**)&p_hsr,  g_hsr);
    cudaGetSymbolAddress((void**)&p_wqr,  g_wqr);
    cudaGetSymbolAddress((void**)&p_wor,  g_wor);

    static int smem_set = 0;
    if (!smem_set) {
        cudaFuncSetAttribute(gemm_tf32_pipe, cudaFuncAttributeMaxDynamicSharedMemorySize,
                             GSTG * GSTF * 4);
        smem_set = 1;
    }

    // launch 0: ba projection + tf32 rounding (fused)
    pre_kernel<<<PREB, 256>>>(hs, w_ba, p_ba, (float4*)p_hsr, (float4*)p_wqr,
                              (float4*)p_wor, (const float4*)w_qkvz, (const float4*)w_out);
    // launch 1: qkvz projection [1024,6144]
    gemm_tf32_pipe<<<dim3(QKVZN / 128, TLEN / 128), 256, GSTG * GSTF * 4>>>(
        p_hsr, p_wqr, p_qkvz, QKVZN, HID);
    // launch 2: fused conv + silu + norms + gates
    convprep_kernel<<<dim3(TLEN, NKH), 128>>>(p_qkvz, conv_w, p_ba, A_log, dt_bias,
                                              p_qn, p_kn, p_v, p_scal);
    // launch 3: delta-rule scan  (ncu captures launch index 3)
    scan_kernel<<<dim3(8, NVH), 128>>>(p_qn, p_kn, p_v, p_scal, p_o);
    // launch 4: gated rmsnorm (tf32-rounded output)
    rmsnorm_kernel<<<dim3(TLEN, NVH), 128>>>(p_o, p_qkvz, norm_w, p_xn);
    // launch 5: output projection [1024,2048]
    gemm_tf32_pipe<<<dim3(HID / 128, TLEN / 128), 256, GSTG * GSTF * 4>>>(
        p_xn, p_wor, out, HID, HID);
}

// round 8
// speedup vs baseline: 1.8968x; 1.1292x over previous
#include <cuda_runtime.h>
#include <cstdint>
#include <math.h>

// ---------------- problem constants ----------------
#define TLEN 1024
#define HID  2048
#define NKH  8
#define NVH  16
#define QKVZN 6144
#define SCALE_Q 0.08838834764831845f   // 128^-0.5

// ---------------- device scratch (no allocation allowed) ----------------
__device__ float g_qkvz[TLEN * QKVZN];
__device__ float g_ba  [TLEN * 32];
__device__ float g_v   [TLEN * 2048];
__device__ float g_qn  [NKH * TLEN * 128];
__device__ float g_kn  [NKH * TLEN * 128];
__device__ float g_scal[NVH * TLEN * 4];
__device__ float g_o   [TLEN * 2048];
__device__ float g_xn  [TLEN * 2048];
__device__ float g_hsr [TLEN * HID];        // tf32-rounded hidden states
__device__ float g_wqr [QKVZN * HID];       // tf32-rounded w_qkvz
__device__ float g_wor [HID * HID];         // tf32-rounded w_out

// ---------------- helpers ----------------
__device__ __forceinline__ float to_tf32(float x) {
    float r;
    asm("cvt.rna.tf32.f32 %0, %1;" : "=f"(r) : "f"(x));
    return r;
}

__device__ __forceinline__ void cp16(void* smem_dst, const void* gmem_src) {
    uint32_t s = (uint32_t)__cvta_generic_to_shared(smem_dst);
    asm volatile("cp.async.cg.shared.global [%0], [%1], 16;\n" :: "r"(s), "l"(gmem_src));
}
#define CP_COMMIT()  asm volatile("cp.async.commit_group;\n")
#define CP_WAIT(n)   asm volatile("cp.async.wait_group %0;\n" :: "n"(n))

__device__ __forceinline__ void mma_tf32(float& d0, float& d1, float& d2, float& d3,
                                         uint32_t a0, uint32_t a1, uint32_t a2, uint32_t a3,
                                         uint32_t b0, uint32_t b1) {
    asm volatile(
        "mma.sync.aligned.m16n8k8.row.col.f32.tf32.tf32.f32 "
        "{%0,%1,%2,%3},{%4,%5,%6,%7},{%8,%9},{%0,%1,%2,%3};"
        : "+f"(d0), "+f"(d1), "+f"(d2), "+f"(d3)
        : "r"(a0), "r"(a1), "r"(a2), "r"(a3), "r"(b0), "r"(b1));
}

// ================= fused pre-pass: ba projection + tf32 rounding =================
#define NH4 (TLEN * HID / 4)
#define NQ4 (QKVZN * HID / 4)
#define NO4 (HID * HID / 4)
#define PREB 4608
__global__ __launch_bounds__(256)
void pre_kernel(const float* __restrict__ hs, const float* __restrict__ wba,
                float* __restrict__ ba_out,
                float4* __restrict__ hsr, float4* __restrict__ wqr,
                float4* __restrict__ wor, const float4* __restrict__ wq4,
                const float4* __restrict__ wo4) {
    const int tid = threadIdx.x;
    if (blockIdx.x < 1024) {
        const int t = blockIdx.x;
        const int n = tid >> 3, s = tid & 7;
        const float4* h4 = (const float4*)(hs + (size_t)t * HID + s * 256);
        const float4* w4 = (const float4*)(wba + (size_t)n * HID + s * 256);
        float acc = 0.f;
#pragma unroll 8
        for (int i = 0; i < 64; i++) {
            float4 a = h4[i], b = w4[i];
            acc += a.x * b.x + a.y * b.y + a.z * b.z + a.w * b.w;
        }
        acc += __shfl_xor_sync(0xffffffffu, acc, 1);
        acc += __shfl_xor_sync(0xffffffffu, acc, 2);
        acc += __shfl_xor_sync(0xffffffffu, acc, 4);
        if (s == 0) ba_out[t * 32 + n] = acc;
    } else {
        const float4* hs4 = (const float4*)hs;
        const int stride = (PREB - 1024) * 256;
        for (int i = (blockIdx.x - 1024) * 256 + tid; i < NH4 + NQ4 + NO4; i += stride) {
            float4 v;
            if (i < NH4) {
                v = hs4[i];
                v.x = to_tf32(v.x); v.y = to_tf32(v.y); v.z = to_tf32(v.z); v.w = to_tf32(v.w);
                hsr[i] = v;
            } else if (i < NH4 + NQ4) {
                v = wq4[i - NH4];
                v.x = to_tf32(v.x); v.y = to_tf32(v.y); v.z = to_tf32(v.z); v.w = to_tf32(v.w);
                wqr[i - NH4] = v;
            } else {
                v = wo4[i - NH4 - NQ4];
                v.x = to_tf32(v.x); v.y = to_tf32(v.y); v.z = to_tf32(v.z); v.w = to_tf32(v.w);
                wor[i - NH4 - NQ4] = v;
            }
        }
    }
}

// ================= tf32 GEMM (cp.async 4-stage): C[M,N] = A[M,K]*B[N,K]^T =======
#define GSTG 4
#define GSTF 5120
__global__ __launch_bounds__(256, 2)
void gemm_tf32_pipe(const float* __restrict__ A, const float* __restrict__ B,
                    float* __restrict__ C, int N, int K) {
    extern __shared__ float sm[];   // GSTG * GSTF floats = 80KB

    const int tid  = threadIdx.x;
    const int warp = tid >> 5, lane = tid & 31;
    const int wm = warp & 1, wn = warp >> 1;
    const int bm = blockIdx.y * 128, bn = blockIdx.x * 128;
    const int r0 = tid >> 2, c4 = tid & 3;

    const float* Ab = A + (size_t)bm * K;
    const float* Bb = B + (size_t)bn * K;
    const int nk = K >> 4;

    float acc[4][4][4];
#pragma unroll
    for (int i = 0; i < 4; i++)
#pragma unroll
        for (int j = 0; j < 4; j++)
#pragma unroll
            for (int l = 0; l < 4; l++) acc[i][j][l] = 0.f;

    auto preload = [&](int kt) {
        const int k0 = (kt << 4) + c4 * 4;
        float* st = sm + (kt & 3) * GSTF;
        cp16(st + r0 * 20 + c4 * 4,                Ab + (size_t)r0 * K + k0);
        cp16(st + (r0 + 64) * 20 + c4 * 4,         Ab + (size_t)(r0 + 64) * K + k0);
        cp16(st + 2560 + r0 * 20 + c4 * 4,         Bb + (size_t)r0 * K + k0);
        cp16(st + 2560 + (r0 + 64) * 20 + c4 * 4,  Bb + (size_t)(r0 + 64) * K + k0);
    };

    preload(0); CP_COMMIT();
    preload(1); CP_COMMIT();
    preload(2); CP_COMMIT();

    for (int kt = 0; kt < nk; kt++) {
        CP_WAIT(2);
        __syncthreads();
        const float* sAb = sm + (kt & 3) * GSTF;
        const float* sBb = sAb + 2560;
#pragma unroll
        for (int ks = 0; ks < 2; ks++) {
            uint32_t af[4][4];
#pragma unroll
            for (int mt = 0; mt < 4; mt++) {
                const float* p = sAb + (wm * 64 + mt * 16 + (lane >> 2)) * 20 + ks * 8 + (lane & 3);
                af[mt][0] = __float_as_uint(p[0]);
                af[mt][1] = __float_as_uint(p[8 * 20]);
                af[mt][2] = __float_as_uint(p[4]);
                af[mt][3] = __float_as_uint(p[8 * 20 + 4]);
            }
            uint32_t bf[4][2];
#pragma unroll
            for (int nt = 0; nt < 4; nt++) {
                const float* p = sBb + (wn * 32 + nt * 8 + (lane >> 2)) * 20 + ks * 8 + (lane & 3);
                bf[nt][0] = __float_as_uint(p[0]);
                bf[nt][1] = __float_as_uint(p[4]);
            }
#pragma unroll
            for (int mt = 0; mt < 4; mt++)
#pragma unroll
                for (int nt = 0; nt < 4; nt++)
                    mma_tf32(acc[mt][nt][0], acc[mt][nt][1], acc[mt][nt][2], acc[mt][nt][3],
                             af[mt][0], af[mt][1], af[mt][2], af[mt][3],
                             bf[nt][0], bf[nt][1]);
        }
        if (kt + 3 < nk) preload(kt + 3);
        CP_COMMIT();
    }

#pragma unroll
    for (int mt = 0; mt < 4; mt++) {
#pragma unroll
        for (int nt = 0; nt < 4; nt++) {
            int row = bm + wm * 64 + mt * 16 + (lane >> 2);
            int col = bn + wn * 32 + nt * 8 + (lane & 3) * 2;
            C[(size_t)row * N + col]           = acc[mt][nt][0];
            C[(size_t)row * N + col + 1]       = acc[mt][nt][1];
            C[(size_t)(row + 8) * N + col]     = acc[mt][nt][2];
            C[(size_t)(row + 8) * N + col + 1] = acc[mt][nt][3];
        }
    }
}

// ================= fused conv1d+silu + l2-norm + gates =================
__global__ __launch_bounds__(128)
void convprep_kernel(const float* __restrict__ qkvz, const float* __restrict__ convw,
                     const float* __restrict__ gba, const float* __restrict__ A_log,
                     const float* __restrict__ dt_bias,
                     float* __restrict__ gqn, float* __restrict__ gkn,
                     float* __restrict__ gv, float* __restrict__ gscal) {
    const int t = blockIdx.x, kh = blockIdx.y, i = threadIdx.x;
    __shared__ float red[4];
    const int base = kh * 768;

    float xq[4], xk[4], xv0[4], xv1[4];
#pragma unroll
    for (int tau = 0; tau < 4; tau++) {
        const int tt = t - 3 + tau;
        const bool ok = (tt >= 0);
        const float* r = qkvz + (size_t)(ok ? tt : 0) * QKVZN + base;
        xq[tau]  = ok ? r[i]       : 0.f;
        xk[tau]  = ok ? r[128 + i] : 0.f;
        xv0[tau] = ok ? r[256 + i] : 0.f;
        xv1[tau] = ok ? r[384 + i] : 0.f;
    }
    const float4 wq  = *(const float4*)(convw + (size_t)(kh * 128 + i) * 4);
    const float4 wk  = *(const float4*)(convw + (size_t)(1024 + kh * 128 + i) * 4);
    const float4 wv0 = *(const float4*)(convw + (size_t)(2048 + (2 * kh) * 128 + i) * 4);
    const float4 wv1 = *(const float4*)(convw + (size_t)(2048 + (2 * kh + 1) * 128 + i) * 4);

    float q  = xq[0] * wq.x + xq[1] * wq.y + xq[2] * wq.z + xq[3] * wq.w;
    float k  = xk[0] * wk.x + xk[1] * wk.y + xk[2] * wk.z + xk[3] * wk.w;
    float v0 = xv0[0] * wv0.x + xv0[1] * wv0.y + xv0[2] * wv0.z + xv0[3] * wv0.w;
    float v1 = xv1[0] * wv1.x + xv1[1] * wv1.y + xv1[2] * wv1.z + xv1[3] * wv1.w;
    q  = q  / (1.f + expf(-q));
    k  = k  / (1.f + expf(-k));
    v0 = v0 / (1.f + expf(-v0));
    v1 = v1 / (1.f + expf(-v1));

    gv[(size_t)t * 2048 + (2 * kh) * 128 + i]     = v0;
    gv[(size_t)t * 2048 + (2 * kh + 1) * 128 + i] = v1;

    float v, s_qq, s_kk, s_qk;

    v = q * q;
#pragma unroll
    for (int m = 16; m; m >>= 1) v += __shfl_xor_sync(0xffffffffu, v, m);
    if ((i & 31) == 0) red[i >> 5] = v;
    __syncthreads();
    s_qq = red[0] + red[1] + red[2] + red[3];
    __syncthreads();

    v = k * k;
#pragma unroll
    for (int m = 16; m; m >>= 1) v += __shfl_xor_sync(0xffffffffu, v, m);
    if ((i & 31) == 0) red[i >> 5] = v;
    __syncthreads();
    s_kk = red[0] + red[1] + red[2] + red[3];
    __syncthreads();

    const float qn = q * rsqrtf(s_qq + 1e-6f) * SCALE_Q;
    const float kn = k * rsqrtf(s_kk + 1e-6f);
    gqn[((size_t)kh * TLEN + t) * 128 + i] = qn;
    gkn[((size_t)kh * TLEN + t) * 128 + i] = kn;

    v = qn * kn;
#pragma unroll
    for (int m = 16; m; m >>= 1) v += __shfl_xor_sync(0xffffffffu, v, m);
    if ((i & 31) == 0) red[i >> 5] = v;
    __syncthreads();
    s_qk = red[0] + red[1] + red[2] + red[3];

    if (i < 2) {
        const int vh = kh * 2 + i;
        const float b = gba[t * 32 + kh * 4 + i];
        const float a = gba[t * 32 + kh * 4 + 2 + i];
        const float beta = 1.f / (1.f + expf(-b));
        const float x = a + dt_bias[vh];
        const float sp = (x > 20.f) ? x : log1pf(expf(x));
        const float g = -expf(A_log[vh]) * sp;
        float4 sc;
        sc.x = expf(g); sc.y = beta; sc.z = s_qk; sc.w = 0.f;
        *(float4*)(gscal + ((size_t)vh * TLEN + t) * 4) = sc;
    }
}

// ================= gated delta-rule scan =================
// grid (8 vblocks, 16 heads), 128 threads = 8 kgroups x 16 vcols.
// 16-slot ring, warp-per-slot group prefetch (1 commit / 4 slots),
// 4-step barrier cadence, prefetch issued before compute.
__global__ __launch_bounds__(128, 1)
void scan_kernel(const float* __restrict__ gqn, const float* __restrict__ gkn,
                 const float* __restrict__ gv, const float* __restrict__ gscal,
                 float* __restrict__ go) {
    const int vb = blockIdx.x;
    const int vh = blockIdx.y;
    const int kh = vh >> 1;
    const int tid = threadIdx.x;
    const int kg = tid & 7;
    const int vc = tid >> 3;

    __shared__ __align__(16) float ring[16][276];  // k[128], q[128], v[16], scal[4]

    const float* kbase = gkn + (size_t)kh * TLEN * 128;
    const float* qbase = gqn + (size_t)kh * TLEN * 128;
    const float* vbase = gv + vh * 128 + vb * 16;
    const float* sbase = gscal + (size_t)vh * TLEN * 4;

    float S[16];
#pragma unroll
    for (int i = 0; i < 16; i++) S[i] = 0.f;

    const int pw = tid >> 5, pl = tid & 31;   // prefetch: warp pw handles slot t0+pw

    // one group = 4 slots, one commit for the whole block
    auto prefetch4 = [&](int t0) {
        const int tt = t0 + pw;
        if (tt < TLEN) {
            float* sl = ring[tt & 15];
            cp16(sl + pl * 4,       kbase + (size_t)tt * 128 + pl * 4);
            cp16(sl + 128 + pl * 4, qbase + (size_t)tt * 128 + pl * 4);
            if (pl < 4) cp16(sl + 256 + pl * 4, vbase + (size_t)tt * 2048 + pl * 4);
            if (pl == 4) cp16(sl + 272, sbase + (size_t)tt * 4);
        }
        CP_COMMIT();
    };

    prefetch4(0);
    prefetch4(4);
    prefetch4(8);

    const int obase = vh * 128 + vb * 16 + vc;

    for (int t = 0; t < TLEN; t += 4) {
        CP_WAIT(2);
        __syncthreads();
        prefetch4(t + 12);   // overlap next group's latency with 4 steps of compute
#pragma unroll
        for (int u = 0; u < 4; u++) {
            const int tt = t + u;
            const float* sl = ring[tt & 15];
            float4 kk[4], qq[4];
            const float4* kp = (const float4*)(sl + kg * 16);
            const float4* qp = (const float4*)(sl + 128 + kg * 16);
#pragma unroll
            for (int j = 0; j < 4; j++) { kk[j] = kp[j]; qq[j] = qp[j]; }

            const float4 sc = *(const float4*)(sl + 272);
            const float eg = sc.x, beta = sc.y, qk = sc.z;
            const float vt = sl[256 + vc];
            const float vtb = vt * beta;
            const float negb = -eg * beta;

            // 4-way split accumulators: chain depth 4 + add tree
            float r1p0, r1p1, r1p2, r1p3, r2p0, r2p1, r2p2, r2p3;
            r1p0 = kk[0].x * S[0];  r2p0 = qq[0].x * S[0];
            r1p1 = kk[1].x * S[4];  r2p1 = qq[1].x * S[4];
            r1p2 = kk[2].x * S[8];  r2p2 = qq[2].x * S[8];
            r1p3 = kk[3].x * S[12]; r2p3 = qq[3].x * S[12];
            r1p0 = fmaf(kk[0].y, S[1],  r1p0); r2p0 = fmaf(qq[0].y, S[1],  r2p0);
            r1p1 = fmaf(kk[1].y, S[5],  r1p1); r2p1 = fmaf(qq[1].y, S[5],  r2p1);
            r1p2 = fmaf(kk[2].y, S[9],  r1p2); r2p2 = fmaf(qq[2].y, S[9],  r2p2);
            r1p3 = fmaf(kk[3].y, S[13], r1p3); r2p3 = fmaf(qq[3].y, S[13], r2p3);
            r1p0 = fmaf(kk[0].z, S[2],  r1p0); r2p0 = fmaf(qq[0].z, S[2],  r2p0);
            r1p1 = fmaf(kk[1].z, S[6],  r1p1); r2p1 = fmaf(qq[1].z, S[6],  r2p1);
            r1p2 = fmaf(kk[2].z, S[10], r1p2); r2p2 = fmaf(qq[2].z, S[10], r2p2);
            r1p3 = fmaf(kk[3].z, S[14], r1p3); r2p3 = fmaf(qq[3].z, S[14], r2p3);
            r1p0 = fmaf(kk[0].w, S[3],  r1p0); r2p0 = fmaf(qq[0].w, S[3],  r2p0);
            r1p1 = fmaf(kk[1].w, S[7],  r1p1); r2p1 = fmaf(qq[1].w, S[7],  r2p1);
            r1p2 = fmaf(kk[2].w, S[11], r1p2); r2p2 = fmaf(qq[2].w, S[11], r2p2);
            r1p3 = fmaf(kk[3].w, S[15], r1p3); r2p3 = fmaf(qq[3].w, S[15], r2p3);

            float r1 = (r1p0 + r1p1) + (r1p2 + r1p3);
            float r2 = (r2p0 + r2p1) + (r2p2 + r2p3);

            r1 += __shfl_xor_sync(0xffffffffu, r1, 1);
            r2 += __shfl_xor_sync(0xffffffffu, r2, 1);
            r1 += __shfl_xor_sync(0xffffffffu, r1, 2);
            r2 += __shfl_xor_sync(0xffffffffu, r2, 2);
            r1 += __shfl_xor_sync(0xffffffffu, r1, 4);
            r2 += __shfl_xor_sync(0xffffffffu, r2, 4);

            // off-path: decayed state (fills the shfl latency window)
            float eS[16];
#pragma unroll
            for (int j = 0; j < 16; j++) eS[j] = eg * S[j];

            const float delta = fmaf(negb, r1, vtb);
            if (kg == 0) go[(size_t)tt * 2048 + obase] = fmaf(eg, r2, qk * delta);
#pragma unroll
            for (int j = 0; j < 4; j++) {
                S[j * 4 + 0] = fmaf(kk[j].x, delta, eS[j * 4 + 0]);
                S[j * 4 + 1] = fmaf(kk[j].y, delta, eS[j * 4 + 1]);
                S[j * 4 + 2] = fmaf(kk[j].z, delta, eS[j * 4 + 2]);
                S[j * 4 + 3] = fmaf(kk[j].w, delta, eS[j * 4 + 3]);
            }
        }
    }
}

// ================= gated RMSNorm (emits tf32-rounded xn) =================
__global__ __launch_bounds__(128)
void rmsnorm_kernel(const float* __restrict__ go, const float* __restrict__ qkvz,
                    const float* __restrict__ nw, float* __restrict__ gxn) {
    const int t = blockIdx.x, vh = blockIdx.y, i = threadIdx.x;
    __shared__ float red[4];
    const float o = go[(size_t)t * 2048 + vh * 128 + i];
    const float z = qkvz[(size_t)t * QKVZN + (vh >> 1) * 768 + 512 + (vh & 1) * 128 + i];
    const float xf = o * (z / (1.f + expf(-z)));
    float v = xf * xf;
#pragma unroll
    for (int m = 16; m; m >>= 1) v += __shfl_xor_sync(0xffffffffu, v, m);
    if ((i & 31) == 0) red[i >> 5] = v;
    __syncthreads();
    const float s = red[0] + red[1] + red[2] + red[3];
    gxn[(size_t)t * 2048 + vh * 128 + i] =
        to_tf32(xf * rsqrtf(s * (1.f / 128.f) + 1e-6f) * nw[i]);
}

// ================= launch =================
extern "C" void kernel_launch(void* const* d_in, const int* in_sizes, int n_in,
                              void* d_out, int out_size) {
    const float* hs      = (const float*)d_in[0];
    const float* w_qkvz  = (const float*)d_in[1];
    const float* w_ba    = (const float*)d_in[2];
    const float* conv_w  = (const float*)d_in[3];
    const float* dt_bias = (const float*)d_in[4];
    const float* A_log   = (const float*)d_in[5];
    const float* norm_w  = (const float*)d_in[6];
    const float* w_out   = (const float*)d_in[7];
    float* out = (float*)d_out;

    float *p_qkvz, *p_ba, *p_v, *p_qn, *p_kn, *p_scal, *p_o, *p_xn;
    float *p_hsr, *p_wqr, *p_wor;
    cudaGetSymbolAddress((void**)&p_qkvz, g_qkvz);
    cudaGetSymbolAddress((void**)&p_ba,   g_ba);
    cudaGetSymbolAddress((void**)&p_v,    g_v);
    cudaGetSymbolAddress((void**)&p_qn,   g_qn);
    cudaGetSymbolAddress((void**)&p_kn,   g_kn);
    cudaGetSymbolAddress((void**)&p_scal, g_scal);
    cudaGetSymbolAddress((void**)&p_o,    g_o);
    cudaGetSymbolAddress((void**)&p_xn,   g_xn);
    cudaGetSymbolAddress((void**)&p_hsr,  g_hsr);
    cudaGetSymbolAddress((void**)&p_wqr,  g_wqr);
    cudaGetSymbolAddress((void**)&p_wor,  g_wor);

    static int smem_set = 0;
    if (!smem_set) {
        cudaFuncSetAttribute(gemm_tf32_pipe, cudaFuncAttributeMaxDynamicSharedMemorySize,
                             GSTG * GSTF * 4);
        smem_set = 1;
    }

    // launch 0: ba projection + tf32 rounding (fused)
    pre_kernel<<<PREB, 256>>>(hs, w_ba, p_ba, (float4*)p_hsr, (float4*)p_wqr,
                              (float4*)p_wor, (const float4*)w_qkvz, (const float4*)w_out);
    // launch 1: qkvz projection [1024,6144]
    gemm_tf32_pipe<<<dim3(QKVZN / 128, TLEN / 128), 256, GSTG * GSTF * 4>>>(
        p_hsr, p_wqr, p_qkvz, QKVZN, HID);
    // launch 2: fused conv + silu + norms + gates
    convprep_kernel<<<dim3(TLEN, NKH), 128>>>(p_qkvz, conv_w, p_ba, A_log, dt_bias,
                                              p_qn, p_kn, p_v, p_scal);
    // launch 3: delta-rule scan  (ncu captures launch index 3)
    scan_kernel<<<dim3(8, NVH), 128>>>(p_qn, p_kn, p_v, p_scal, p_o);
    // launch 4: gated rmsnorm (tf32-rounded output)
    rmsnorm_kernel<<<dim3(TLEN, NVH), 128>>>(p_o, p_qkvz, norm_w, p_xn);
    // launch 5: output projection [1024,2048]
    gemm_tf32_pipe<<<dim3(HID / 128, TLEN / 128), 256, GSTG * GSTF * 4>>>(
        p_xn, p_wor, out, HID, HID);
}

// round 9
// speedup vs baseline: 2.1969x; 1.1582x over previous
#include <cuda_runtime.h>
#include <cstdint>
#include <math.h>

// ---------------- problem constants ----------------
#define TLEN 1024
#define HID  2048
#define NKH  8
#define NVH  16
#define QKVZN 6144
#define SCALE_Q 0.08838834764831845f   // 128^-0.5

// ---------------- device scratch (no allocation allowed) ----------------
__device__ float g_qkvz[TLEN * QKVZN];
__device__ float g_ba  [TLEN * 32];
__device__ float g_v   [TLEN * 2048];
__device__ float g_qn  [NKH * TLEN * 128];
__device__ float g_kn  [NKH * TLEN * 128];
__device__ float g_scal[NVH * TLEN * 4];
__device__ float g_o   [TLEN * 2048];
__device__ float g_xn  [TLEN * 2048];
__device__ float g_hsr [TLEN * HID];        // tf32-rounded hidden states
__device__ float g_wqr [QKVZN * HID];       // tf32-rounded w_qkvz
__device__ float g_wor [HID * HID];         // tf32-rounded w_out

// ---------------- helpers ----------------
__device__ __forceinline__ float to_tf32(float x) {
    float r;
    asm("cvt.rna.tf32.f32 %0, %1;" : "=f"(r) : "f"(x));
    return r;
}

__device__ __forceinline__ void cp16(void* smem_dst, const void* gmem_src) {
    uint32_t s = (uint32_t)__cvta_generic_to_shared(smem_dst);
    asm volatile("cp.async.cg.shared.global [%0], [%1], 16;\n" :: "r"(s), "l"(gmem_src));
}
#define CP_COMMIT()  asm volatile("cp.async.commit_group;\n")
#define CP_WAIT(n)   asm volatile("cp.async.wait_group %0;\n" :: "n"(n))

__device__ __forceinline__ void mma_tf32(float& d0, float& d1, float& d2, float& d3,
                                         uint32_t a0, uint32_t a1, uint32_t a2, uint32_t a3,
                                         uint32_t b0, uint32_t b1) {
    asm volatile(
        "mma.sync.aligned.m16n8k8.row.col.f32.tf32.tf32.f32 "
        "{%0,%1,%2,%3},{%4,%5,%6,%7},{%8,%9},{%0,%1,%2,%3};"
        : "+f"(d0), "+f"(d1), "+f"(d2), "+f"(d3)
        : "r"(a0), "r"(a1), "r"(a2), "r"(a3), "r"(b0), "r"(b1));
}

// ================= fused pre-pass: ba projection + tf32 rounding =================
#define NH4 (TLEN * HID / 4)
#define NQ4 (QKVZN * HID / 4)
#define NO4 (HID * HID / 4)
#define PREB 4608
__global__ __launch_bounds__(256)
void pre_kernel(const float* __restrict__ hs, const float* __restrict__ wba,
                float* __restrict__ ba_out,
                float4* __restrict__ hsr, float4* __restrict__ wqr,
                float4* __restrict__ wor, const float4* __restrict__ wq4,
                const float4* __restrict__ wo4) {
    const int tid = threadIdx.x;
    if (blockIdx.x < 1024) {
        const int t = blockIdx.x;
        const int n = tid >> 3, s = tid & 7;
        const float4* h4 = (const float4*)(hs + (size_t)t * HID + s * 256);
        const float4* w4 = (const float4*)(wba + (size_t)n * HID + s * 256);
        float acc = 0.f;
#pragma unroll 8
        for (int i = 0; i < 64; i++) {
            float4 a = h4[i], b = w4[i];
            acc += a.x * b.x + a.y * b.y + a.z * b.z + a.w * b.w;
        }
        acc += __shfl_xor_sync(0xffffffffu, acc, 1);
        acc += __shfl_xor_sync(0xffffffffu, acc, 2);
        acc += __shfl_xor_sync(0xffffffffu, acc, 4);
        if (s == 0) ba_out[t * 32 + n] = acc;
    } else {
        const float4* hs4 = (const float4*)hs;
        const int stride = (PREB - 1024) * 256;
        for (int i = (blockIdx.x - 1024) * 256 + tid; i < NH4 + NQ4 + NO4; i += stride) {
            float4 v;
            if (i < NH4) {
                v = hs4[i];
                v.x = to_tf32(v.x); v.y = to_tf32(v.y); v.z = to_tf32(v.z); v.w = to_tf32(v.w);
                hsr[i] = v;
            } else if (i < NH4 + NQ4) {
                v = wq4[i - NH4];
                v.x = to_tf32(v.x); v.y = to_tf32(v.y); v.z = to_tf32(v.z); v.w = to_tf32(v.w);
                wqr[i - NH4] = v;
            } else {
                v = wo4[i - NH4 - NQ4];
                v.x = to_tf32(v.x); v.y = to_tf32(v.y); v.z = to_tf32(v.z); v.w = to_tf32(v.w);
                wor[i - NH4 - NQ4] = v;
            }
        }
    }
}

// ================= tf32 GEMM (cp.async 4-stage): C[M,N] = A[M,K]*B[N,K]^T =======
#define GSTG 4
#define GSTF 5120
__global__ __launch_bounds__(256, 2)
void gemm_tf32_pipe(const float* __restrict__ A, const float* __restrict__ B,
                    float* __restrict__ C, int N, int K) {
    extern __shared__ float sm[];   // GSTG * GSTF floats = 80KB

    const int tid  = threadIdx.x;
    const int warp = tid >> 5, lane = tid & 31;
    const int wm = warp & 1, wn = warp >> 1;
    const int bm = blockIdx.y * 128, bn = blockIdx.x * 128;
    const int r0 = tid >> 2, c4 = tid & 3;

    const float* Ab = A + (size_t)bm * K;
    const float* Bb = B + (size_t)bn * K;
    const int nk = K >> 4;

    float acc[4][4][4];
#pragma unroll
    for (int i = 0; i < 4; i++)
#pragma unroll
        for (int j = 0; j < 4; j++)
#pragma unroll
            for (int l = 0; l < 4; l++) acc[i][j][l] = 0.f;

    auto preload = [&](int kt) {
        const int k0 = (kt << 4) + c4 * 4;
        float* st = sm + (kt & 3) * GSTF;
        cp16(st + r0 * 20 + c4 * 4,                Ab + (size_t)r0 * K + k0);
        cp16(st + (r0 + 64) * 20 + c4 * 4,         Ab + (size_t)(r0 + 64) * K + k0);
        cp16(st + 2560 + r0 * 20 + c4 * 4,         Bb + (size_t)r0 * K + k0);
        cp16(st + 2560 + (r0 + 64) * 20 + c4 * 4,  Bb + (size_t)(r0 + 64) * K + k0);
    };

    preload(0); CP_COMMIT();
    preload(1); CP_COMMIT();
    preload(2); CP_COMMIT();

    for (int kt = 0; kt < nk; kt++) {
        CP_WAIT(2);
        __syncthreads();
        const float* sAb = sm + (kt & 3) * GSTF;
        const float* sBb = sAb + 2560;
#pragma unroll
        for (int ks = 0; ks < 2; ks++) {
            uint32_t af[4][4];
#pragma unroll
            for (int mt = 0; mt < 4; mt++) {
                const float* p = sAb + (wm * 64 + mt * 16 + (lane >> 2)) * 20 + ks * 8 + (lane & 3);
                af[mt][0] = __float_as_uint(p[0]);
                af[mt][1] = __float_as_uint(p[8 * 20]);
                af[mt][2] = __float_as_uint(p[4]);
                af[mt][3] = __float_as_uint(p[8 * 20 + 4]);
            }
            uint32_t bf[4][2];
#pragma unroll
            for (int nt = 0; nt < 4; nt++) {
                const float* p = sBb + (wn * 32 + nt * 8 + (lane >> 2)) * 20 + ks * 8 + (lane & 3);
                bf[nt][0] = __float_as_uint(p[0]);
                bf[nt][1] = __float_as_uint(p[4]);
            }
#pragma unroll
            for (int mt = 0; mt < 4; mt++)
#pragma unroll
                for (int nt = 0; nt < 4; nt++)
                    mma_tf32(acc[mt][nt][0], acc[mt][nt][1], acc[mt][nt][2], acc[mt][nt][3],
                             af[mt][0], af[mt][1], af[mt][2], af[mt][3],
                             bf[nt][0], bf[nt][1]);
        }
        if (kt + 3 < nk) preload(kt + 3);
        CP_COMMIT();
    }

#pragma unroll
    for (int mt = 0; mt < 4; mt++) {
#pragma unroll
        for (int nt = 0; nt < 4; nt++) {
            int row = bm + wm * 64 + mt * 16 + (lane >> 2);
            int col = bn + wn * 32 + nt * 8 + (lane & 3) * 2;
            C[(size_t)row * N + col]           = acc[mt][nt][0];
            C[(size_t)row * N + col + 1]       = acc[mt][nt][1];
            C[(size_t)(row + 8) * N + col]     = acc[mt][nt][2];
            C[(size_t)(row + 8) * N + col + 1] = acc[mt][nt][3];
        }
    }
}

// ================= fused conv1d+silu + l2-norm + gates =================
__global__ __launch_bounds__(128)
void convprep_kernel(const float* __restrict__ qkvz, const float* __restrict__ convw,
                     const float* __restrict__ gba, const float* __restrict__ A_log,
                     const float* __restrict__ dt_bias,
                     float* __restrict__ gqn, float* __restrict__ gkn,
                     float* __restrict__ gv, float* __restrict__ gscal) {
    const int t = blockIdx.x, kh = blockIdx.y, i = threadIdx.x;
    __shared__ float red[4];
    const int base = kh * 768;

    float xq[4], xk[4], xv0[4], xv1[4];
#pragma unroll
    for (int tau = 0; tau < 4; tau++) {
        const int tt = t - 3 + tau;
        const bool ok = (tt >= 0);
        const float* r = qkvz + (size_t)(ok ? tt : 0) * QKVZN + base;
        xq[tau]  = ok ? r[i]       : 0.f;
        xk[tau]  = ok ? r[128 + i] : 0.f;
        xv0[tau] = ok ? r[256 + i] : 0.f;
        xv1[tau] = ok ? r[384 + i] : 0.f;
    }
    const float4 wq  = *(const float4*)(convw + (size_t)(kh * 128 + i) * 4);
    const float4 wk  = *(const float4*)(convw + (size_t)(1024 + kh * 128 + i) * 4);
    const float4 wv0 = *(const float4*)(convw + (size_t)(2048 + (2 * kh) * 128 + i) * 4);
    const float4 wv1 = *(const float4*)(convw + (size_t)(2048 + (2 * kh + 1) * 128 + i) * 4);

    float q  = xq[0] * wq.x + xq[1] * wq.y + xq[2] * wq.z + xq[3] * wq.w;
    float k  = xk[0] * wk.x + xk[1] * wk.y + xk[2] * wk.z + xk[3] * wk.w;
    float v0 = xv0[0] * wv0.x + xv0[1] * wv0.y + xv0[2] * wv0.z + xv0[3] * wv0.w;
    float v1 = xv1[0] * wv1.x + xv1[1] * wv1.y + xv1[2] * wv1.z + xv1[3] * wv1.w;
    q  = q  / (1.f + expf(-q));
    k  = k  / (1.f + expf(-k));
    v0 = v0 / (1.f + expf(-v0));
    v1 = v1 / (1.f + expf(-v1));

    gv[(size_t)t * 2048 + (2 * kh) * 128 + i]     = v0;
    gv[(size_t)t * 2048 + (2 * kh + 1) * 128 + i] = v1;

    float v, s_qq, s_kk, s_qk;

    v = q * q;
#pragma unroll
    for (int m = 16; m; m >>= 1) v += __shfl_xor_sync(0xffffffffu, v, m);
    if ((i & 31) == 0) red[i >> 5] = v;
    __syncthreads();
    s_qq = red[0] + red[1] + red[2] + red[3];
    __syncthreads();

    v = k * k;
#pragma unroll
    for (int m = 16; m; m >>= 1) v += __shfl_xor_sync(0xffffffffu, v, m);
    if ((i & 31) == 0) red[i >> 5] = v;
    __syncthreads();
    s_kk = red[0] + red[1] + red[2] + red[3];
    __syncthreads();

    const float qn = q * rsqrtf(s_qq + 1e-6f) * SCALE_Q;
    const float kn = k * rsqrtf(s_kk + 1e-6f);
    gqn[((size_t)kh * TLEN + t) * 128 + i] = qn;
    gkn[((size_t)kh * TLEN + t) * 128 + i] = kn;

    v = qn * kn;
#pragma unroll
    for (int m = 16; m; m >>= 1) v += __shfl_xor_sync(0xffffffffu, v, m);
    if ((i & 31) == 0) red[i >> 5] = v;
    __syncthreads();
    s_qk = red[0] + red[1] + red[2] + red[3];

    if (i < 2) {
        const int vh = kh * 2 + i;
        const float b = gba[t * 32 + kh * 4 + i];
        const float a = gba[t * 32 + kh * 4 + 2 + i];
        const float beta = 1.f / (1.f + expf(-b));
        const float x = a + dt_bias[vh];
        const float sp = (x > 20.f) ? x : log1pf(expf(x));
        const float g = -expf(A_log[vh]) * sp;
        float4 sc;
        sc.x = expf(g); sc.y = beta; sc.z = s_qk; sc.w = 0.f;
        *(float4*)(gscal + ((size_t)vh * TLEN + t) * 4) = sc;
    }
}

// ================= gated delta-rule scan =================
// grid (8 vblocks, 16 heads), 256 threads = 16 kgroups x 16 vcols
// (2 warps per SMSP for latency interleave). 16-slot ring, warp-pair per
// slot prefetch, 4-step barrier cadence.
__global__ __launch_bounds__(256, 1)
void scan_kernel(const float* __restrict__ gqn, const float* __restrict__ gkn,
                 const float* __restrict__ gv, const float* __restrict__ gscal,
                 float* __restrict__ go) {
    const int vb = blockIdx.x;
    const int vh = blockIdx.y;
    const int kh = vh >> 1;
    const int tid = threadIdx.x;
    const int kg = tid & 15;      // k group (8 k-slots each)
    const int vc = tid >> 4;      // v col within block (0..15)

    __shared__ __align__(16) float ring[16][276];  // k[128], q[128], v[16], scal[4]

    const float* kbase = gkn + (size_t)kh * TLEN * 128;
    const float* qbase = gqn + (size_t)kh * TLEN * 128;
    const float* vbase = gv + vh * 128 + vb * 16;
    const float* sbase = gscal + (size_t)vh * TLEN * 4;

    float S[8];
#pragma unroll
    for (int i = 0; i < 8; i++) S[i] = 0.f;

    const int pw = tid >> 5, pl = tid & 31;   // 8 warps: pair (2w,2w+1) owns slot t0+w

    // one group = 4 slots, one commit for the whole block
    auto prefetch4 = [&](int t0) {
        const int tt = t0 + (pw >> 1);
        if (tt < TLEN) {
            float* sl = ring[tt & 15];
            if ((pw & 1) == 0) {
                cp16(sl + pl * 4, kbase + (size_t)tt * 128 + pl * 4);
                if (pl < 4) cp16(sl + 256 + pl * 4, vbase + (size_t)tt * 2048 + pl * 4);
                if (pl == 4) cp16(sl + 272, sbase + (size_t)tt * 4);
            } else {
                cp16(sl + 128 + pl * 4, qbase + (size_t)tt * 128 + pl * 4);
            }
        }
        CP_COMMIT();
    };

    prefetch4(0);
    prefetch4(4);
    prefetch4(8);

    const int obase = vh * 128 + vb * 16 + vc;

    for (int t = 0; t < TLEN; t += 4) {
        CP_WAIT(2);
        __syncthreads();
        prefetch4(t + 12);   // overlap next group's latency with 4 steps of compute
#pragma unroll
        for (int u = 0; u < 4; u++) {
            const int tt = t + u;
            const float* sl = ring[tt & 15];
            const float4* kp = (const float4*)(sl + kg * 8);
            const float4* qp = (const float4*)(sl + 128 + kg * 8);
            const float4 k0 = kp[0], k1 = kp[1];
            const float4 q0 = qp[0], q1 = qp[1];

            const float4 sc = *(const float4*)(sl + 272);
            const float eg = sc.x, beta = sc.y, qk = sc.z;
            const float vt = sl[256 + vc];
            const float vtb = vt * beta;
            const float negb = -eg * beta;

            // 2-way split accumulators: chain depth 4 + 1 add
            float r1a, r1b, r2a, r2b;
            r1a = k0.x * S[0];               r2a = q0.x * S[0];
            r1b = k1.x * S[4];               r2b = q1.x * S[4];
            r1a = fmaf(k0.y, S[1], r1a);     r2a = fmaf(q0.y, S[1], r2a);
            r1b = fmaf(k1.y, S[5], r1b);     r2b = fmaf(q1.y, S[5], r2b);
            r1a = fmaf(k0.z, S[2], r1a);     r2a = fmaf(q0.z, S[2], r2a);
            r1b = fmaf(k1.z, S[6], r1b);     r2b = fmaf(q1.z, S[6], r2b);
            r1a = fmaf(k0.w, S[3], r1a);     r2a = fmaf(q0.w, S[3], r2a);
            r1b = fmaf(k1.w, S[7], r1b);     r2b = fmaf(q1.w, S[7], r2b);

            float r1 = r1a + r1b;
            float r2 = r2a + r2b;

            // reduce over 16 kgroups (lanes l and l^{1,2,4,8} share vc)
            r1 += __shfl_xor_sync(0xffffffffu, r1, 1);
            r2 += __shfl_xor_sync(0xffffffffu, r2, 1);
            r1 += __shfl_xor_sync(0xffffffffu, r1, 2);
            r2 += __shfl_xor_sync(0xffffffffu, r2, 2);
            r1 += __shfl_xor_sync(0xffffffffu, r1, 4);
            r2 += __shfl_xor_sync(0xffffffffu, r2, 4);
            r1 += __shfl_xor_sync(0xffffffffu, r1, 8);
            r2 += __shfl_xor_sync(0xffffffffu, r2, 8);

            // off-path: decayed state (fills the shfl latency window)
            float eS[8];
#pragma unroll
            for (int j = 0; j < 8; j++) eS[j] = eg * S[j];

            const float delta = fmaf(negb, r1, vtb);
            if (kg == 0) go[(size_t)tt * 2048 + obase] = fmaf(eg, r2, qk * delta);

            S[0] = fmaf(k0.x, delta, eS[0]);
            S[1] = fmaf(k0.y, delta, eS[1]);
            S[2] = fmaf(k0.z, delta, eS[2]);
            S[3] = fmaf(k0.w, delta, eS[3]);
            S[4] = fmaf(k1.x, delta, eS[4]);
            S[5] = fmaf(k1.y, delta, eS[5]);
            S[6] = fmaf(k1.z, delta, eS[6]);
            S[7] = fmaf(k1.w, delta, eS[7]);
        }
    }
}

// ================= gated RMSNorm (emits tf32-rounded xn) =================
__global__ __launch_bounds__(128)
void rmsnorm_kernel(const float* __restrict__ go, const float* __restrict__ qkvz,
                    const float* __restrict__ nw, float* __restrict__ gxn) {
    const int t = blockIdx.x, vh = blockIdx.y, i = threadIdx.x;
    __shared__ float red[4];
    const float o = go[(size_t)t * 2048 + vh * 128 + i];
    const float z = qkvz[(size_t)t * QKVZN + (vh >> 1) * 768 + 512 + (vh & 1) * 128 + i];
    const float xf = o * (z / (1.f + expf(-z)));
    float v = xf * xf;
#pragma unroll
    for (int m = 16; m; m >>= 1) v += __shfl_xor_sync(0xffffffffu, v, m);
    if ((i & 31) == 0) red[i >> 5] = v;
    __syncthreads();
    const float s = red[0] + red[1] + red[2] + red[3];
    gxn[(size_t)t * 2048 + vh * 128 + i] =
        to_tf32(xf * rsqrtf(s * (1.f / 128.f) + 1e-6f) * nw[i]);
}

// ================= launch =================
extern "C" void kernel_launch(void* const* d_in, const int* in_sizes, int n_in,
                              void* d_out, int out_size) {
    const float* hs      = (const float*)d_in[0];
    const float* w_qkvz  = (const float*)d_in[1];
    const float* w_ba    = (const float*)d_in[2];
    const float* conv_w  = (const float*)d_in[3];
    const float* dt_bias = (const float*)d_in[4];
    const float* A_log   = (const float*)d_in[5];
    const float* norm_w  = (const float*)d_in[6];
    const float* w_out   = (const float*)d_in[7];
    float* out = (float*)d_out;

    float *p_qkvz, *p_ba, *p_v, *p_qn, *p_kn, *p_scal, *p_o, *p_xn;
    float *p_hsr, *p_wqr, *p_wor;
    cudaGetSymbolAddress((void**)&p_qkvz, g_qkvz);
    cudaGetSymbolAddress((void**)&p_ba,   g_ba);
    cudaGetSymbolAddress((void**)&p_v,    g_v);
    cudaGetSymbolAddress((void**)&p_qn,   g_qn);
    cudaGetSymbolAddress((void**)&p_kn,   g_kn);
    cudaGetSymbolAddress((void**)&p_scal, g_scal);
    cudaGetSymbolAddress((void**)&p_o,    g_o);
    cudaGetSymbolAddress((void**)&p_xn,   g_xn);
    cudaGetSymbolAddress((void**)&p_hsr,  g_hsr);
    cudaGetSymbolAddress((void**)&p_wqr,  g_wqr);
    cudaGetSymbolAddress((void**)&p_wor,  g_wor);

    static int smem_set = 0;
    if (!smem_set) {
        cudaFuncSetAttribute(gemm_tf32_pipe, cudaFuncAttributeMaxDynamicSharedMemorySize,
                             GSTG * GSTF * 4);
        smem_set = 1;
    }

    // launch 0: ba projection + tf32 rounding (fused)
    pre_kernel<<<PREB, 256>>>(hs, w_ba, p_ba, (float4*)p_hsr, (float4*)p_wqr,
                              (float4*)p_wor, (const float4*)w_qkvz, (const float4*)w_out);
    // launch 1: qkvz projection [1024,6144]
    gemm_tf32_pipe<<<dim3(QKVZN / 128, TLEN / 128), 256, GSTG * GSTF * 4>>>(
        p_hsr, p_wqr, p_qkvz, QKVZN, HID);
    // launch 2: fused conv + silu + norms + gates
    convprep_kernel<<<dim3(TLEN, NKH), 128>>>(p_qkvz, conv_w, p_ba, A_log, dt_bias,
                                              p_qn, p_kn, p_v, p_scal);
    // launch 3: delta-rule scan  (ncu captures launch index 3)
    scan_kernel<<<dim3(8, NVH), 256>>>(p_qn, p_kn, p_v, p_scal, p_o);
    // launch 4: gated rmsnorm (tf32-rounded output)
    rmsnorm_kernel<<<dim3(TLEN, NVH), 128>>>(p_o, p_qkvz, norm_w, p_xn);
    // launch 5: output projection [1024,2048]
    gemm_tf32_pipe<<<dim3(HID / 128, TLEN / 128), 256, GSTG * GSTF * 4>>>(
        p_xn, p_wor, out, HID, HID);
}